// round 2
// baseline (speedup 1.0000x reference)
#include <cuda_runtime.h>
#include <cuda_bf16.h>
#include <cstdint>

// CycleEmbedding: out[c, :] += emb[x[a], :] for each edge e with
// a = atom_to_cycle[0][e], c = atom_to_cycle[1][e].
// x: [N=100000] int32 (values 0..21)  -- JAX x64 disabled => int32 despite "int64"
// atom_to_cycle: [2, E=600000] int32
// emb_weight: [22, 128] float32
// out: [100000, 128] float32

#define HIDDEN 128
#define NUM_CODES 22

__global__ void zero_out_kernel(float4* __restrict__ out, int n4) {
    int idx = blockIdx.x * blockDim.x + threadIdx.x;
    int stride = gridDim.x * blockDim.x;
    for (int i = idx; i < n4; i += stride) {
        out[i] = make_float4(0.f, 0.f, 0.f, 0.f);
    }
}

__global__ void __launch_bounds__(256) scatter_kernel(
    const int* __restrict__ x,            // [N]
    const int* __restrict__ atom_idx,     // [E]
    const int* __restrict__ cycle_idx,    // [E]
    const float* __restrict__ emb,        // [22, 128]
    float* __restrict__ out,              // [S, 128]
    int E)
{
    __shared__ float s_emb[NUM_CODES * HIDDEN];

    // cooperatively stage the embedding table (11 KB)
    for (int i = threadIdx.x; i < NUM_CODES * HIDDEN; i += blockDim.x)
        s_emb[i] = emb[i];
    __syncthreads();

    const int lane = threadIdx.x & 31;
    const int warp_global = (blockIdx.x * blockDim.x + threadIdx.x) >> 5;
    const int num_warps = (gridDim.x * blockDim.x) >> 5;

    for (int e = warp_global; e < E; e += num_warps) {
        // warp-uniform index loads (broadcast in L1)
        int a = __ldg(&atom_idx[e]);
        int c = __ldg(&cycle_idx[e]);
        int code = __ldg(&x[a]);

        // lane l handles floats [4l, 4l+4)
        const float4* src = reinterpret_cast<const float4*>(&s_emb[code * HIDDEN]) + lane;
        float4 v = *src;

        float* dst = out + (size_t)c * HIDDEN + lane * 4;
        asm volatile(
            "red.global.add.v4.f32 [%0], {%1, %2, %3, %4};\n"
            :: "l"(dst), "f"(v.x), "f"(v.y), "f"(v.z), "f"(v.w)
            : "memory");
    }
}

extern "C" void kernel_launch(void* const* d_in, const int* in_sizes, int n_in,
                              void* d_out, int out_size)
{
    const int*   x   = (const int*)d_in[0];
    const int*   a2c = (const int*)d_in[1];
    const float* emb = (const float*)d_in[2];
    float*       out = (float*)d_out;

    const int E = in_sizes[1] / 2;           // 600000
    const int* atom_idx  = a2c;
    const int* cycle_idx = a2c + E;

    // 1) zero the output (poisoned by harness)
    int n4 = out_size / 4;                    // float4 count
    {
        int threads = 256;
        int blocks = (n4 + threads - 1) / threads;
        if (blocks > 8192) blocks = 8192;     // grid-stride
        zero_out_kernel<<<blocks, threads>>>((float4*)out, n4);
    }

    // 2) scatter-add: one warp per edge
    {
        int threads = 256;                    // 8 warps/block
        int blocks = (E + 7) / 8;
        if (blocks > 75000) blocks = 75000;
        scatter_kernel<<<blocks, threads>>>(x, atom_idx, cycle_idx, emb, out, E);
    }
}

// round 3
// speedup vs baseline: 2.0401x; 2.0401x over previous
#include <cuda_runtime.h>
#include <cuda_bf16.h>
#include <cstdint>

// CycleEmbedding: out[c, :] += emb[x[a], :] per edge.
// x: [100000] int32 (0..21), atom_to_cycle: [2, 600000] int32,
// emb_weight: [22,128] f32, out: [100000,128] f32.

#define HIDDEN 128
#define NUM_CODES 22
#define TILE 2048
#define THREADS 256

__global__ void zero_out_kernel(float4* __restrict__ out, int n4) {
    int idx = blockIdx.x * blockDim.x + threadIdx.x;
    if (idx < n4) out[idx] = make_float4(0.f, 0.f, 0.f, 0.f);
}

__global__ void __launch_bounds__(THREADS) scatter_kernel(
    const int* __restrict__ x,            // [N]
    const int* __restrict__ atom_idx,     // [E]
    const int* __restrict__ cycle_idx,    // [E]
    const float* __restrict__ emb,        // [22, 128]
    float* __restrict__ out,              // [S, 128]
    int E)
{
    __shared__ float s_emb[NUM_CODES * HIDDEN];   // 11 KB
    __shared__ int   s_idx[TILE];                 // packed (code<<20)|cycle, 8 KB

    // stage embedding table once
    for (int i = threadIdx.x; i < NUM_CODES * HIDDEN; i += THREADS)
        s_emb[i] = emb[i];

    const int tile0 = blockIdx.x * TILE;
    const int cnt = min(TILE, E - tile0);

    // stage + pack indices for this tile (coalesced; x[a] gather once per edge)
    for (int i = threadIdx.x; i < cnt; i += THREADS) {
        int e = tile0 + i;
        int a = __ldg(&atom_idx[e]);
        int c = __ldg(&cycle_idx[e]);
        int code = __ldg(&x[a]);
        s_idx[i] = (code << 20) | c;
    }
    __syncthreads();

    const int lane = threadIdx.x & 31;
    const int warp = threadIdx.x >> 5;            // 0..7
    const uint32_t lane_off = (uint32_t)lane << 4;  // lane*16 bytes
    char* const outb = (char*)out;
    const char* const embb = (const char*)s_emb;

    #pragma unroll 4
    for (int i = warp; i < cnt; i += THREADS / 32) {
        int packed = s_idx[i];                    // warp-uniform LDS.32 (broadcast)
        uint32_t c    = (uint32_t)packed & 0xFFFFFu;
        uint32_t code = (uint32_t)packed >> 20;

        // lane handles bytes [lane*16, lane*16+16) of the 512B row
        float4 v = *reinterpret_cast<const float4*>(embb + ((code << 9) | lane_off));
        char* dst = outb + (((size_t)(c << 9)) + lane_off);
        asm volatile(
            "red.global.add.v4.f32 [%0], {%1, %2, %3, %4};\n"
            :: "l"(dst), "f"(v.x), "f"(v.y), "f"(v.z), "f"(v.w)
            : "memory");
    }
}

extern "C" void kernel_launch(void* const* d_in, const int* in_sizes, int n_in,
                              void* d_out, int out_size)
{
    const int*   x   = (const int*)d_in[0];
    const int*   a2c = (const int*)d_in[1];
    const float* emb = (const float*)d_in[2];
    float*       out = (float*)d_out;

    const int E = in_sizes[1] / 2;                // 600000
    const int* atom_idx  = a2c;
    const int* cycle_idx = a2c + E;

    // 1) zero output (harness poisons it)
    int n4 = out_size / 4;
    zero_out_kernel<<<(n4 + THREADS - 1) / THREADS, THREADS>>>((float4*)out, n4);

    // 2) tiled scatter-add
    int blocks = (E + TILE - 1) / TILE;           // 293
    scatter_kernel<<<blocks, THREADS>>>(x, atom_idx, cycle_idx, emb, out, E);
}

// round 4
// speedup vs baseline: 2.1812x; 1.0692x over previous
#include <cuda_runtime.h>
#include <cuda_bf16.h>
#include <cstdint>

// CycleEmbedding: out[c, :] += emb[x[a], :] per edge.
// x: [100000] int32 (0..21), atom_to_cycle: [2, 600000] int32,
// emb_weight: [22,128] f32, out: [100000,128] f32.

#define HIDDEN 128
#define NUM_CODES 22
#define TILE 1024
#define THREADS 512

__global__ void zero_out_kernel(float4* __restrict__ out, int n4) {
    int idx = blockIdx.x * blockDim.x + threadIdx.x;
    if (idx < n4) out[idx] = make_float4(0.f, 0.f, 0.f, 0.f);
}

__global__ void __launch_bounds__(THREADS) scatter_kernel(
    const int* __restrict__ x,            // [N]
    const int* __restrict__ atom_idx,     // [E]
    const int* __restrict__ cycle_idx,    // [E]
    const float* __restrict__ emb,        // [22, 128]
    float* __restrict__ out,              // [S, 128]
    int E)
{
    __shared__ float s_emb[NUM_CODES * HIDDEN];   // 11 KB
    __shared__ int   s_idx[TILE];                 // packed (code<<20)|cycle, 4 KB

    // stage embedding table once per block
    for (int i = threadIdx.x; i < NUM_CODES * HIDDEN; i += THREADS)
        s_emb[i] = emb[i];

    const int tile0 = blockIdx.x * TILE;
    const int cnt = min(TILE, E - tile0);

    // stage + pack indices for this tile (coalesced; x[a] gather once per edge)
    for (int i = threadIdx.x; i < cnt; i += THREADS) {
        int e = tile0 + i;
        int a = __ldg(&atom_idx[e]);
        int c = __ldg(&cycle_idx[e]);
        int code = __ldg(&x[a]);
        s_idx[i] = (code << 20) | c;
    }
    __syncthreads();

    const int lane = threadIdx.x & 31;
    const int warp = threadIdx.x >> 5;              // 0..15
    const uint32_t lane_off = (uint32_t)lane << 4;  // lane*16 bytes
    char* const outb = (char*)out;
    const char* const embb = (const char*)s_emb;

    #pragma unroll 4
    for (int i = warp; i < cnt; i += THREADS / 32) {
        int packed = s_idx[i];                      // warp-uniform LDS.32 (broadcast)
        uint32_t c    = (uint32_t)packed & 0xFFFFFu;
        uint32_t code = (uint32_t)packed >> 20;

        // lane handles bytes [lane*16, lane*16+16) of the 512B row
        float4 v = *reinterpret_cast<const float4*>(embb + ((code << 9) | lane_off));
        char* dst = outb + (((size_t)(c << 9)) + lane_off);
        asm volatile(
            "red.global.add.v4.f32 [%0], {%1, %2, %3, %4};\n"
            :: "l"(dst), "f"(v.x), "f"(v.y), "f"(v.z), "f"(v.w)
            : "memory");
    }
}

extern "C" void kernel_launch(void* const* d_in, const int* in_sizes, int n_in,
                              void* d_out, int out_size)
{
    const int*   x   = (const int*)d_in[0];
    const int*   a2c = (const int*)d_in[1];
    const float* emb = (const float*)d_in[2];
    float*       out = (float*)d_out;

    const int E = in_sizes[1] / 2;                // 600000
    const int* atom_idx  = a2c;
    const int* cycle_idx = a2c + E;

    // 1) zero output (harness poisons it)
    int n4 = out_size / 4;
    zero_out_kernel<<<(n4 + 255) / 256, 256>>>((float4*)out, n4);

    // 2) tiled scatter-add, sized for ~full occupancy (586 blocks, 4 CTA/SM)
    int blocks = (E + TILE - 1) / TILE;
    scatter_kernel<<<blocks, THREADS>>>(x, atom_idx, cycle_idx, emb, out, E);
}

// round 5
// speedup vs baseline: 2.9279x; 1.3423x over previous
#include <cuda_runtime.h>
#include <cuda_bf16.h>
#include <cstdint>

// CycleEmbedding via code-count factorization:
//   out[c,:] = sum_k count[c,k] * emb[k,:],  count[c,k] = #{e: cycle_e=c, x[atom_e]=k}
// x: [100000] int32 (0..21), atom_to_cycle: [2, 600000] int32,
// emb_weight: [22,128] f32, out: [100000,128] f32.

#define HIDDEN 128
#define NUM_CODES 22
#define MAX_SEGMENTS 100000

__device__ int g_counts[MAX_SEGMENTS * NUM_CODES];   // 8.8 MB scratch

__global__ void zero_counts_kernel(int n4) {
    int idx = blockIdx.x * blockDim.x + threadIdx.x;
    if (idx < n4) reinterpret_cast<int4*>(g_counts)[idx] = make_int4(0, 0, 0, 0);
}

__global__ void __launch_bounds__(256) count_kernel(
    const int* __restrict__ x,
    const int* __restrict__ atom_idx,
    const int* __restrict__ cycle_idx,
    int E)
{
    int e = blockIdx.x * blockDim.x + threadIdx.x;
    if (e >= E) return;
    int a = __ldg(&atom_idx[e]);
    int c = __ldg(&cycle_idx[e]);
    int code = __ldg(&x[a]);
    atomicAdd(&g_counts[c * NUM_CODES + code], 1);   // compiles to RED (no return use)
}

__global__ void __launch_bounds__(256) expand_kernel(
    const float* __restrict__ emb,       // [22, 128]
    float* __restrict__ out,             // [S, 128]
    int S)
{
    __shared__ float s_emb[NUM_CODES * HIDDEN];      // 11 KB
    for (int i = threadIdx.x; i < NUM_CODES * HIDDEN; i += blockDim.x)
        s_emb[i] = emb[i];
    __syncthreads();

    const int lane = threadIdx.x & 31;
    const int warp = threadIdx.x >> 5;               // 0..7
    const int row = blockIdx.x * 8 + warp;
    if (row >= S) return;

    // lanes 0..21 load this row's counts (88B contiguous)
    int cnt = (lane < NUM_CODES) ? g_counts[row * NUM_CODES + lane] : 0;

    float4 acc = make_float4(0.f, 0.f, 0.f, 0.f);
    const float4* embv = reinterpret_cast<const float4*>(s_emb);

    #pragma unroll
    for (int k = 0; k < NUM_CODES; k++) {
        int ck = __shfl_sync(0xffffffffu, cnt, k);
        if (ck) {
            float f = (float)ck;
            float4 e = embv[k * 32 + lane];          // LDS.128, conflict-free phases
            acc.x += f * e.x; acc.y += f * e.y;
            acc.z += f * e.z; acc.w += f * e.w;
        }
    }

    reinterpret_cast<float4*>(out)[(size_t)row * 32 + lane] = acc;
}

extern "C" void kernel_launch(void* const* d_in, const int* in_sizes, int n_in,
                              void* d_out, int out_size)
{
    const int*   x   = (const int*)d_in[0];
    const int*   a2c = (const int*)d_in[1];
    const float* emb = (const float*)d_in[2];
    float*       out = (float*)d_out;

    const int E = in_sizes[1] / 2;                   // 600000
    const int S = out_size / HIDDEN;                 // 100000
    const int* atom_idx  = a2c;
    const int* cycle_idx = a2c + E;

    // 1) zero the counter table (NUM_CODES*S divisible by 4? 22*100000 = 2.2M, /4 = 550000)
    int n4 = (S * NUM_CODES) / 4;
    zero_counts_kernel<<<(n4 + 255) / 256, 256>>>(n4);

    // 2) histogram edges into (cycle, code) counts
    count_kernel<<<(E + 255) / 256, 256>>>(x, atom_idx, cycle_idx, E);

    // 3) expand counts -> output rows (one warp per row)
    expand_kernel<<<(S + 7) / 8, 256>>>(emb, out, S);
}